// round 8
// baseline (speedup 1.0000x reference)
#include <cuda_runtime.h>
#include <cuda_fp16.h>
#include <cstdint>
#include <math.h>

#define B_ 32
#define N_ 8192
#define D_ 1024
#define H_ 128
#define NSPLIT 32

// ---------------- scratch (no cudaMalloc allowed) ----------------
__device__ __align__(16) unsigned short g_w1t[H_ * D_];   // fp16 W1^T [h][d]
__device__ __align__(16) float g_e[B_ * N_];              // mask*exp(logit)
__device__ __align__(16) float g_erow[B_ * N_ / 128];     // per-CTA partial sums (2048)
__device__ __align__(16) float g_esum[B_];                // per-batch sums
__device__ __align__(16) float g_part[B_ * NSPLIT * D_];

// ---------------- helpers ----------------
__device__ __forceinline__ uint32_t smem_u32(const void* p) {
    uint32_t a;
    asm("{ .reg .u64 t; cvta.to.shared.u64 t, %1; cvt.u32.u64 %0, t; }" : "=r"(a) : "l"(p));
    return a;
}
__device__ __forceinline__ void cpasync16(uint32_t dst, const void* src) {
    asm volatile("cp.async.cg.shared.global [%0], [%1], 16;"
                 :: "r"(dst), "l"(src) : "memory");
}
__device__ __forceinline__ void ldm4(uint32_t* r, uint32_t addr) {
    asm volatile("ldmatrix.sync.aligned.m8n8.x4.shared.b16 {%0,%1,%2,%3}, [%4];"
                 : "=r"(r[0]), "=r"(r[1]), "=r"(r[2]), "=r"(r[3]) : "r"(addr));
}
__device__ __forceinline__ void mma16816(float* c, const uint32_t* a,
                                         uint32_t b0, uint32_t b1) {
    asm volatile(
        "mma.sync.aligned.m16n8k16.row.col.f32.f16.f16.f32 "
        "{%0,%1,%2,%3}, {%4,%5,%6,%7}, {%8,%9}, {%0,%1,%2,%3};"
        : "+f"(c[0]), "+f"(c[1]), "+f"(c[2]), "+f"(c[3])
        : "r"(a[0]), "r"(a[1]), "r"(a[2]), "r"(a[3]), "r"(b0), "r"(b1));
}
__device__ __forceinline__ uint32_t h2pack(float2 f) {
    __half2 h = __floats2half2_rn(f.x, f.y);
    return *(uint32_t*)&h;
}

// ---------------- kernel 0: W1^T -> fp16 ----------------
__global__ void prep_kernel(const float* __restrict__ w1) {
    int idx = blockIdx.x * 256 + threadIdx.x;   // 0..H*D-1
    int h = idx >> 10, d = idx & 1023;
    g_w1t[idx] = __half_as_ushort(__float2half_rn(w1[(size_t)d * H_ + h]));
}

// ---------------- kernel 1: fused GEMM1 + tanh + fc2 + exp*mask ----------------
// A fragments loaded DIRECTLY from gmem (fp32 -> fp16 pack); B via cp.async smem.
static constexpr int ROWE = 72;
static constexpr int ROWB = 144;                 // 128B data + 16B pad
static constexpr int TILE = 128 * ROWB;          // 18432
static constexpr int OFF_BB0  = 0;
static constexpr int OFF_BB1  = TILE;
static constexpr int OFF_PART = 2 * TILE;        // 256 floats
static constexpr int SMEM_BYTES = 2 * TILE + 1024;  // 37888

__global__ void __launch_bounds__(256, 2)
gemm1_kernel(const float* __restrict__ feats, const float* __restrict__ b1,
             const float* __restrict__ w2, const float* __restrict__ b2,
             const int* __restrict__ mask) {
    extern __shared__ char dsm[];
    uint32_t sb = smem_u32(dsm);
    float* part = (float*)(dsm + OFF_PART);

    int tid = threadIdx.x;
    int lane = tid & 31, warp = tid >> 5;
    int warp_m = warp >> 1, warp_n = warp & 1;   // 4 x 2 warp grid
    int m_base = warp_m * 32, n_base = warp_n * 64;
    int gid = lane >> 2, tig = lane & 3;

    const float* A0 = feats + (size_t)blockIdx.x * 128 * D_;
    // A row pointers for the two 16-row tiles of this warp
    const float* ap[2][2];
    ap[0][0] = A0 + (size_t)(m_base + gid) * D_;
    ap[0][1] = ap[0][0] + 8 * D_;
    ap[1][0] = A0 + (size_t)(m_base + 16 + gid) * D_;
    ap[1][1] = ap[1][0] + 8 * D_;

    // B ldmatrix per-lane offsets (validated in R3: identical results to wmma)
    uint32_t boff[4];
    #pragma unroll
    for (int njp = 0; njp < 4; njp++) {
        int rowB = n_base + njp * 16 + (lane & 7) + ((lane >> 4) & 1) * 8;
        boff[njp] = (uint32_t)(rowB * ROWB + ((lane >> 3) & 1) * 16);
    }

    // B cp.async staging indices
    int bn = tid >> 3, bcu = tid & 7;

    float c[2][8][4];
    #pragma unroll
    for (int mi = 0; mi < 2; mi++)
        #pragma unroll
        for (int ni = 0; ni < 8; ni++)
            #pragma unroll
            for (int q = 0; q < 4; q++) c[mi][ni][q] = 0.0f;

    auto cpa_b = [&](int kc, int buf) {
        uint32_t dbb = sb + (buf ? OFF_BB1 : OFF_BB0);
        #pragma unroll
        for (int i = 0; i < 4; i++) {
            int n = bn + i * 32;
            cpasync16(dbb + (uint32_t)(n * ROWB + bcu * 16),
                      g_w1t + (size_t)n * D_ + kc * 64 + bcu * 8);
        }
        asm volatile("cp.async.commit_group;" ::: "memory");
    };

    // ---- prologue ----
    cpa_b(0, 0);
    asm volatile("cp.async.wait_group 0;" ::: "memory");
    __syncthreads();

    // ---- main loop ----
    #pragma unroll 1
    for (int kc = 0; kc < 16; kc++) {
        int buf = kc & 1;
        if (kc < 15) cpa_b(kc + 1, buf ^ 1);
        uint32_t sbB = sb + (buf ? OFF_BB1 : OFF_BB0);

        #pragma unroll
        for (int ks = 0; ks < 4; ks++) {
            int k0 = kc * 64 + ks * 16 + 2 * tig;
            // A fragments direct from gmem (PTX m16n8k16 A layout)
            uint32_t a[2][4];
            #pragma unroll
            for (int mi = 0; mi < 2; mi++) {
                a[mi][0] = h2pack(__ldg((const float2*)(ap[mi][0] + k0)));
                a[mi][1] = h2pack(__ldg((const float2*)(ap[mi][1] + k0)));
                a[mi][2] = h2pack(__ldg((const float2*)(ap[mi][0] + k0 + 8)));
                a[mi][3] = h2pack(__ldg((const float2*)(ap[mi][1] + k0 + 8)));
            }
            #pragma unroll
            for (int njp = 0; njp < 4; njp++) {
                uint32_t bh[4];
                ldm4(bh, sbB + boff[njp] + ks * 32);
                int n0 = njp * 2, n1 = n0 + 1;
                mma16816(c[0][n0], a[0], bh[0], bh[1]);
                mma16816(c[1][n0], a[1], bh[0], bh[1]);
                mma16816(c[0][n1], a[0], bh[2], bh[3]);
                mma16816(c[1][n1], a[1], bh[2], bh[3]);
            }
        }
        if (kc < 15) asm volatile("cp.async.wait_group 0;" ::: "memory");
        __syncthreads();
    }

    // ---- epilogue: p(row) = sum_j w2_j * tanh(c + b1_j) ----
    float p[2][2] = {{0.f, 0.f}, {0.f, 0.f}};
    #pragma unroll
    for (int mi = 0; mi < 2; mi++) {
        #pragma unroll
        for (int ni = 0; ni < 8; ni++) {
            int col0 = n_base + ni * 8 + 2 * tig;
            float w0 = __ldg(w2 + col0), w1v = __ldg(w2 + col0 + 1);
            float bb0 = __ldg(b1 + col0), bb1 = __ldg(b1 + col0 + 1);
            p[mi][0] += w0 * tanhf(c[mi][ni][0] + bb0) + w1v * tanhf(c[mi][ni][1] + bb1);
            p[mi][1] += w0 * tanhf(c[mi][ni][2] + bb0) + w1v * tanhf(c[mi][ni][3] + bb1);
        }
    }
    #pragma unroll
    for (int mi = 0; mi < 2; mi++)
        #pragma unroll
        for (int hf = 0; hf < 2; hf++) {
            float v = p[mi][hf];
            v += __shfl_xor_sync(0xffffffffu, v, 1);
            v += __shfl_xor_sync(0xffffffffu, v, 2);
            if (tig == 0) {
                int row = m_base + mi * 16 + hf * 8 + gid;
                part[row * 2 + warp_n] = v;
            }
        }
    __syncthreads();

    // logit -> e = mask * exp(logit); no max-stabilizer needed (|logit| <= ||w2||_1 ~ 9)
    float e = 0.0f;
    int batch = blockIdx.x >> 6;
    int nidx = ((blockIdx.x & 63) << 7) + tid;
    if (tid < 128) {
        float logit = part[tid * 2] + part[tid * 2 + 1] + b2[0];
        int m = mask[(size_t)batch * N_ + nidx];
        e = m ? expf(logit) : 0.0f;
        g_e[(size_t)batch * N_ + nidx] = e;
    }
    __syncthreads();              // part reads done; safe to reuse
    if (tid < 128) part[tid] = e;
    __syncthreads();
    #pragma unroll
    for (int o = 64; o > 0; o >>= 1) {
        if (tid < o) part[tid] += part[tid + o];
        __syncthreads();
    }
    if (tid == 0) g_erow[blockIdx.x] = part[0];
}

// ---------------- kernel 2: per-batch sum of e (deterministic) ----------------
__global__ void esum_kernel() {
    __shared__ float red[64];
    int b = blockIdx.x, t = threadIdx.x;
    red[t] = g_erow[b * 64 + t];
    __syncthreads();
    #pragma unroll
    for (int o = 32; o > 0; o >>= 1) {
        if (t < o) red[t] += red[t + o];
        __syncthreads();
    }
    if (t == 0) g_esum[b] = red[0];
}

// ---------------- kernel 3: pooled partials + attn output ----------------
__global__ void __launch_bounds__(256)
pooled_part_kernel(const float* __restrict__ feats, float* __restrict__ attn) {
    __shared__ float sa[256];
    int b = blockIdx.x, s = blockIdx.y, t = threadIdx.x;
    size_t n0 = (size_t)s * 256;
    float inv = 1.0f / fmaxf(g_esum[b], 1e-8f);
    float a0 = g_e[(size_t)b * N_ + n0 + t] * inv;
    sa[t] = a0;
    attn[(size_t)b * N_ + n0 + t] = a0;
    __syncthreads();
    const float4* fp = (const float4*)(feats + ((size_t)b * N_ + n0) * D_);
    float4 acc = make_float4(0.f, 0.f, 0.f, 0.f);
    #pragma unroll 4
    for (int n = 0; n < 256; n++) {
        float a = sa[n];
        float4 v = __ldg(fp + (size_t)n * 256 + t);
        acc.x += a * v.x; acc.y += a * v.y; acc.z += a * v.z; acc.w += a * v.w;
    }
    ((float4*)(g_part + ((size_t)b * NSPLIT + s) * D_))[t] = acc;
}

// ---------------- kernel 4: reduce partials -> pooled ----------------
__global__ void reduce_kernel(float* __restrict__ pooled) {
    int idx = blockIdx.x * 256 + threadIdx.x;
    int b = idx >> 10, d = idx & 1023;
    float acc = 0.0f;
    #pragma unroll
    for (int s = 0; s < NSPLIT; s++)
        acc += g_part[((size_t)b * NSPLIT + s) * D_ + d];
    pooled[idx] = acc;
}

// ---------------- kernel 5: final classifier ----------------
__global__ void final_kernel(const float* __restrict__ pooled,
                             const float* __restrict__ wc,
                             const float* __restrict__ bc,
                             float* __restrict__ logits) {
    __shared__ float red[256];
    int b = blockIdx.x, t = threadIdx.x;
    float acc = 0.0f;
    #pragma unroll
    for (int j = 0; j < 4; j++) {
        int d = t + j * 256;
        acc += pooled[(size_t)b * D_ + d] * wc[d];
    }
    red[t] = acc; __syncthreads();
    for (int o = 128; o > 0; o >>= 1) { if (t < o) red[t] += red[t + o]; __syncthreads(); }
    if (t == 0) logits[b] = red[0] + bc[0];
}

// ---------------- launch ----------------
extern "C" void kernel_launch(void* const* d_in, const int* in_sizes, int n_in,
                              void* d_out, int out_size) {
    const float* feats = (const float*)d_in[0];
    const int* mask = (const int*)d_in[1];       // jnp.bool_ -> int32
    const float* w1 = (const float*)d_in[2];
    const float* b1 = (const float*)d_in[3];
    const float* w2 = (const float*)d_in[4];
    const float* b2 = (const float*)d_in[5];
    const float* wc = (const float*)d_in[6];
    const float* bc = (const float*)d_in[7];

    float* out = (float*)d_out;
    float* out_logits = out;                 // [B]
    float* out_pooled = out + B_;            // [B, D]
    float* out_attn   = out + B_ + B_ * D_;  // [B, N]

    cudaFuncSetAttribute(gemm1_kernel,
                         cudaFuncAttributeMaxDynamicSharedMemorySize, SMEM_BYTES);

    prep_kernel<<<(H_ * D_) / 256, 256>>>(w1);
    gemm1_kernel<<<(B_ * N_) / 128, 256, SMEM_BYTES>>>(feats, b1, w2, b2, mask);
    esum_kernel<<<B_, 64>>>();
    pooled_part_kernel<<<dim3(B_, NSPLIT), 256>>>(feats, out_attn);
    reduce_kernel<<<(B_ * D_) / 256, 256>>>(out_pooled);
    final_kernel<<<B_, 256>>>(out_pooled, wc, bc, out_logits);
}

// round 9
// speedup vs baseline: 1.2943x; 1.2943x over previous
#include <cuda_runtime.h>
#include <cuda_fp16.h>
#include <mma.h>
#include <cstdint>
#include <math.h>

using namespace nvcuda;

#define B_ 32
#define N_ 8192
#define D_ 1024
#define H_ 128
#define NSPLIT 32

// ---------------- scratch (no cudaMalloc allowed) ----------------
__device__ __align__(16) unsigned short g_w1t[H_ * D_];   // fp16 W1^T [h][d]
__device__ __align__(16) float g_e[B_ * N_];              // mask*exp(logit)
__device__ __align__(16) float g_erow[B_ * N_ / 128];     // per-CTA partial sums
__device__ __align__(16) float g_esum[B_];                // per-batch sums
__device__ __align__(16) float g_part[B_ * NSPLIT * D_];

// ---------------- helpers ----------------
__device__ __forceinline__ uint32_t smem_u32(const void* p) {
    uint32_t a;
    asm("{ .reg .u64 t; cvta.to.shared.u64 t, %1; cvt.u32.u64 %0, t; }" : "=r"(a) : "l"(p));
    return a;
}
__device__ __forceinline__ void cpasync16(uint32_t dst, const void* src) {
    asm volatile("cp.async.cg.shared.global [%0], [%1], 16;"
                 :: "r"(dst), "l"(src) : "memory");
}

// ---------------- kernel 0: W1^T -> fp16 ----------------
__global__ void prep_kernel(const float* __restrict__ w1) {
    int idx = blockIdx.x * 256 + threadIdx.x;   // 0..H*D-1
    int h = idx >> 10, d = idx & 1023;
    g_w1t[idx] = __half_as_ushort(__float2half_rn(w1[(size_t)d * H_ + h]));
}

// ---------------- kernel 1: fused GEMM1 + tanh + fc2 + exp*mask ----------------
static constexpr int ROWE = 72;                  // row stride in fp16 elements
static constexpr int ROWB = 144;                 // row stride bytes (128 data + 16 pad)
static constexpr int TILE = 128 * ROWB;          // 18432 bytes per 128x64 tile
static constexpr int OFF_B1   = 0;               // 512 B
static constexpr int OFF_W2   = 512;             // 512 B
static constexpr int OFF_PART = 1024;            // 1024 B
static constexpr int OFF_SCR  = 2048;            // 8 warps * 256 floats = 8192 B
static constexpr int OFF_A0   = 10240;           // A fp16 ping-pong
static constexpr int OFF_A1   = OFF_A0 + TILE;
static constexpr int OFF_BB0  = OFF_A1 + TILE;   // B fp16 ping-pong
static constexpr int OFF_BB1  = OFF_BB0 + TILE;
static constexpr int SMEM_BYTES = OFF_BB1 + TILE;   // 83968

__global__ void __launch_bounds__(256, 2)
gemm1_kernel(const float* __restrict__ feats, const float* __restrict__ b1,
             const float* __restrict__ w2, const float* __restrict__ b2,
             const int* __restrict__ mask) {
    extern __shared__ char dsm[];
    uint32_t sb = smem_u32(dsm);
    float* b1s  = (float*)(dsm + OFF_B1);
    float* w2s  = (float*)(dsm + OFF_W2);
    float* part = (float*)(dsm + OFF_PART);
    float* scr  = (float*)(dsm + OFF_SCR);

    int tid = threadIdx.x;
    int lane = tid & 31, warp = tid >> 5;
    int warp_m = warp >> 1, warp_n = warp & 1;   // 4 x 2 warp grid
    int m_base = warp_m * 32, n_base = warp_n * 64;

    if (tid < 128) { b1s[tid] = b1[tid]; w2s[tid] = w2[tid]; }

    const float* A0 = feats + (size_t)blockIdx.x * 128 * D_;

    // staging indices
    int ar = tid >> 4, ac4 = tid & 15;   // A: 8 iters x (row, float4-col)
    int bn = tid >> 3, bcu = tid & 7;    // B: 4 iters x (row, 16B-col)

    wmma::fragment<wmma::accumulator, 16, 16, 16, float> cfr[2][4];
    #pragma unroll
    for (int mi = 0; mi < 2; mi++)
        #pragma unroll
        for (int ni = 0; ni < 4; ni++)
            wmma::fill_fragment(cfr[mi][ni], 0.0f);

    auto ldg_a = [&](float4* av, int kc) {
        #pragma unroll
        for (int i = 0; i < 8; i++) {
            int r = ar + i * 16;
            av[i] = __ldg((const float4*)(A0 + (size_t)r * D_ + kc * 64) + ac4);
        }
    };
    auto sts_a = [&](const float4* av, int buf) {
        uint32_t base = sb + (buf ? OFF_A1 : OFF_A0);
        #pragma unroll
        for (int i = 0; i < 8; i++) {
            int r = ar + i * 16;
            uint32_t off = (uint32_t)(r * ROWB + ac4 * 8);
            __half2 h01 = __floats2half2_rn(av[i].x, av[i].y);
            __half2 h23 = __floats2half2_rn(av[i].z, av[i].w);
            asm volatile("st.shared.v2.b32 [%0], {%1, %2};"
                         :: "r"(base + off),
                            "r"(*(uint32_t*)&h01), "r"(*(uint32_t*)&h23) : "memory");
        }
    };
    auto cpa_b = [&](int kc, int buf) {
        uint32_t dbb = sb + (buf ? OFF_BB1 : OFF_BB0);
        #pragma unroll
        for (int i = 0; i < 4; i++) {
            int n = bn + i * 32;
            cpasync16(dbb + (uint32_t)(n * ROWB + bcu * 16),
                      g_w1t + (size_t)n * D_ + kc * 64 + bcu * 8);
        }
        asm volatile("cp.async.commit_group;" ::: "memory");
    };
    auto compute = [&](int buf) {
        const __half* As = (const __half*)(dsm + (buf ? OFF_A1 : OFF_A0));
        const __half* Bs = (const __half*)(dsm + (buf ? OFF_BB1 : OFF_BB0));
        #pragma unroll
        for (int ks = 0; ks < 4; ks++) {
            wmma::fragment<wmma::matrix_a, 16, 16, 16, __half, wmma::row_major> af[2];
            #pragma unroll
            for (int mi = 0; mi < 2; mi++) {
                const __half* pa = As + (size_t)(m_base + mi * 16) * ROWE + ks * 16;
                wmma::load_matrix_sync(af[mi], pa, ROWE);
            }
            #pragma unroll
            for (int ni = 0; ni < 4; ni++) {
                wmma::fragment<wmma::matrix_b, 16, 16, 16, __half, wmma::col_major> bf;
                const __half* pb = Bs + (size_t)(n_base + ni * 16) * ROWE + ks * 16;
                wmma::load_matrix_sync(bf, pb, ROWE);
                #pragma unroll
                for (int mi = 0; mi < 2; mi++)
                    wmma::mma_sync(cfr[mi][ni], af[mi], bf, cfr[mi][ni]);
            }
        }
    };

    // ---- prologue: stage chunk 0 into buffer 0 ----
    {
        float4 av[8];
        cpa_b(0, 0);
        ldg_a(av, 0);
        sts_a(av, 0);
        asm volatile("cp.async.wait_group 0;" ::: "memory");
    }
    __syncthreads();

    // ---- main loop: both A and B double-buffered, ONE sync per chunk ----
    #pragma unroll 1
    for (int kc = 0; kc < 16; kc++) {
        int buf = kc & 1;
        float4 av[8];
        if (kc < 15) {
            ldg_a(av, kc + 1);          // DRAM latency hides under compute
            cpa_b(kc + 1, buf ^ 1);     // B prefetch into idle buffer
        }
        compute(buf);
        if (kc < 15) {
            sts_a(av, buf ^ 1);         // writes idle buffer; no conflict
            asm volatile("cp.async.wait_group 0;" ::: "memory");
        }
        __syncthreads();
    }

    // ---- epilogue: p(row) = sum_j w2_j * tanh(c + b1_j) ----
    float* ws = scr + warp * 256;
    int r16 = lane & 15, ch = (lane >> 4) * 8;
    float pacc[2] = {0.0f, 0.0f};
    #pragma unroll
    for (int mi = 0; mi < 2; mi++) {
        #pragma unroll
        for (int ni = 0; ni < 4; ni++) {
            wmma::store_matrix_sync(ws, cfr[mi][ni], 16, wmma::mem_row_major);
            __syncwarp();
            float s = 0.0f;
            #pragma unroll
            for (int j = 0; j < 8; j++) {
                int col = n_base + ni * 16 + ch + j;
                float v = ws[r16 * 16 + ch + j];
                s += w2s[col] * tanhf(v + b1s[col]);
            }
            pacc[mi] += s;
            __syncwarp();
        }
    }
    #pragma unroll
    for (int mi = 0; mi < 2; mi++) {
        float tot = pacc[mi] + __shfl_xor_sync(0xffffffffu, pacc[mi], 16);
        if (lane < 16) {
            int row = m_base + mi * 16 + r16;
            part[row * 2 + warp_n] = tot;
        }
    }
    __syncthreads();

    // logit -> e = mask * exp(logit); no max-stabilizer needed (|logit| <= ||w2||_1)
    float e = 0.0f;
    int batch = blockIdx.x >> 6;
    int nidx = ((blockIdx.x & 63) << 7) + tid;
    if (tid < 128) {
        float logit = part[tid * 2] + part[tid * 2 + 1] + b2[0];
        int m = mask[(size_t)batch * N_ + nidx];
        e = m ? expf(logit) : 0.0f;
        g_e[(size_t)batch * N_ + nidx] = e;
    }
    __syncthreads();              // part reads done; safe to reuse
    if (tid < 128) part[tid] = e;
    __syncthreads();
    #pragma unroll
    for (int o = 64; o > 0; o >>= 1) {
        if (tid < o) part[tid] += part[tid + o];
        __syncthreads();
    }
    if (tid == 0) g_erow[blockIdx.x] = part[0];
}

// ---------------- kernel 2: per-batch sum of e (deterministic) ----------------
__global__ void esum_kernel() {
    __shared__ float red[64];
    int b = blockIdx.x, t = threadIdx.x;
    red[t] = g_erow[b * 64 + t];
    __syncthreads();
    #pragma unroll
    for (int o = 32; o > 0; o >>= 1) {
        if (t < o) red[t] += red[t + o];
        __syncthreads();
    }
    if (t == 0) g_esum[b] = red[0];
}

// ---------------- kernel 3: pooled partials + attn output ----------------
__global__ void __launch_bounds__(256)
pooled_part_kernel(const float* __restrict__ feats, float* __restrict__ attn) {
    __shared__ float sa[256];
    int b = blockIdx.x, s = blockIdx.y, t = threadIdx.x;
    size_t n0 = (size_t)s * 256;
    float inv = 1.0f / fmaxf(g_esum[b], 1e-8f);
    float a0 = g_e[(size_t)b * N_ + n0 + t] * inv;
    sa[t] = a0;
    attn[(size_t)b * N_ + n0 + t] = a0;
    __syncthreads();
    const float4* fp = (const float4*)(feats + ((size_t)b * N_ + n0) * D_);
    float4 acc = make_float4(0.f, 0.f, 0.f, 0.f);
    #pragma unroll 4
    for (int n = 0; n < 256; n++) {
        float a = sa[n];
        float4 v = __ldg(fp + (size_t)n * 256 + t);
        acc.x += a * v.x; acc.y += a * v.y; acc.z += a * v.z; acc.w += a * v.w;
    }
    ((float4*)(g_part + ((size_t)b * NSPLIT + s) * D_))[t] = acc;
}

// ---------------- kernel 4: reduce partials -> pooled ----------------
__global__ void reduce_kernel(float* __restrict__ pooled) {
    int idx = blockIdx.x * 256 + threadIdx.x;
    int b = idx >> 10, d = idx & 1023;
    float acc = 0.0f;
    #pragma unroll
    for (int s = 0; s < NSPLIT; s++)
        acc += g_part[((size_t)b * NSPLIT + s) * D_ + d];
    pooled[idx] = acc;
}

// ---------------- kernel 5: final classifier ----------------
__global__ void final_kernel(const float* __restrict__ pooled,
                             const float* __restrict__ wc,
                             const float* __restrict__ bc,
                             float* __restrict__ logits) {
    __shared__ float red[256];
    int b = blockIdx.x, t = threadIdx.x;
    float acc = 0.0f;
    #pragma unroll
    for (int j = 0; j < 4; j++) {
        int d = t + j * 256;
        acc += pooled[(size_t)b * D_ + d] * wc[d];
    }
    red[t] = acc; __syncthreads();
    for (int o = 128; o > 0; o >>= 1) { if (t < o) red[t] += red[t + o]; __syncthreads(); }
    if (t == 0) logits[b] = red[0] + bc[0];
}

// ---------------- launch ----------------
extern "C" void kernel_launch(void* const* d_in, const int* in_sizes, int n_in,
                              void* d_out, int out_size) {
    const float* feats = (const float*)d_in[0];
    const int* mask = (const int*)d_in[1];       // jnp.bool_ -> int32
    const float* w1 = (const float*)d_in[2];
    const float* b1 = (const float*)d_in[3];
    const float* w2 = (const float*)d_in[4];
    const float* b2 = (const float*)d_in[5];
    const float* wc = (const float*)d_in[6];
    const float* bc = (const float*)d_in[7];

    float* out = (float*)d_out;
    float* out_logits = out;                 // [B]
    float* out_pooled = out + B_;            // [B, D]
    float* out_attn   = out + B_ + B_ * D_;  // [B, N]

    cudaFuncSetAttribute(gemm1_kernel,
                         cudaFuncAttributeMaxDynamicSharedMemorySize, SMEM_BYTES);

    prep_kernel<<<(H_ * D_) / 256, 256>>>(w1);
    gemm1_kernel<<<(B_ * N_) / 128, 256, SMEM_BYTES>>>(feats, b1, w2, b2, mask);
    esum_kernel<<<B_, 64>>>();
    pooled_part_kernel<<<dim3(B_, NSPLIT), 256>>>(feats, out_attn);
    reduce_kernel<<<(B_ * D_) / 256, 256>>>(out_pooled);
    final_kernel<<<B_, 256>>>(out_pooled, wc, bc, out_logits);
}

// round 10
// speedup vs baseline: 1.4763x; 1.1406x over previous
#include <cuda_runtime.h>
#include <cuda_fp16.h>
#include <mma.h>
#include <cstdint>
#include <math.h>

using namespace nvcuda;

#define B_ 32
#define N_ 8192
#define D_ 1024
#define H_ 128
#define CPB 64          // CTAs per batch in gemm1 (8192/128)

// ---------------- scratch (no cudaMalloc allowed) ----------------
__device__ __align__(16) unsigned short g_w1t[H_ * D_];   // fp16 W1^T [h][d]
__device__ __align__(16) float g_e[B_ * N_];              // mask*exp(logit)
__device__ __align__(16) float g_erow[B_ * CPB];          // per-CTA e sums
__device__ __align__(16) float g_esum[B_];                // per-batch sums
__device__ __align__(16) float g_part[B_ * CPB * D_];     // unscaled pooled partials (8 MB)

// ---------------- helpers ----------------
__device__ __forceinline__ uint32_t smem_u32(const void* p) {
    uint32_t a;
    asm("{ .reg .u64 t; cvta.to.shared.u64 t, %1; cvt.u32.u64 %0, t; }" : "=r"(a) : "l"(p));
    return a;
}
__device__ __forceinline__ void cpasync16(uint32_t dst, const void* src) {
    asm volatile("cp.async.cg.shared.global [%0], [%1], 16;"
                 :: "r"(dst), "l"(src) : "memory");
}

// ---------------- kernel 0: W1^T -> fp16 ----------------
__global__ void prep_kernel(const float* __restrict__ w1) {
    int idx = blockIdx.x * 256 + threadIdx.x;   // 0..H*D-1
    int h = idx >> 10, d = idx & 1023;
    g_w1t[idx] = __half_as_ushort(__float2half_rn(w1[(size_t)d * H_ + h]));
}

// ---------------- kernel 1: GEMM1 + tanh + fc2 + exp*mask + weighted pool ----------------
static constexpr int ROWE = 72;                  // row stride in fp16 elements
static constexpr int ROWB = 144;                 // row stride bytes (128 data + 16 pad)
static constexpr int TILE = 128 * ROWB;          // 18432 bytes per 128x64 tile
static constexpr int OFF_B1   = 0;               // 512 B
static constexpr int OFF_W2   = 512;             // 512 B
static constexpr int OFF_PART = 1024;            // 1024 B
static constexpr int OFF_SCR  = 2048;            // 8 warps * 256 floats = 8192 B
static constexpr int OFF_A0   = 10240;           // A fp16 ping-pong
static constexpr int OFF_A1   = OFF_A0 + TILE;
static constexpr int OFF_BB0  = OFF_A1 + TILE;   // B fp16 ping-pong
static constexpr int OFF_BB1  = OFF_BB0 + TILE;
static constexpr int SMEM_BYTES = OFF_BB1 + TILE;   // 83968

__global__ void __launch_bounds__(256, 2)
gemm1_kernel(const float* __restrict__ feats, const float* __restrict__ b1,
             const float* __restrict__ w2, const float* __restrict__ b2,
             const int* __restrict__ mask) {
    extern __shared__ char dsm[];
    uint32_t sb = smem_u32(dsm);
    float* b1s  = (float*)(dsm + OFF_B1);
    float* w2s  = (float*)(dsm + OFF_W2);
    float* part = (float*)(dsm + OFF_PART);
    float* scr  = (float*)(dsm + OFF_SCR);
    float* sa   = scr;                            // e values [128] (post-epilogue reuse)

    int tid = threadIdx.x;
    int lane = tid & 31, warp = tid >> 5;
    int warp_m = warp >> 1, warp_n = warp & 1;   // 4 x 2 warp grid
    int m_base = warp_m * 32, n_base = warp_n * 64;

    if (tid < 128) { b1s[tid] = b1[tid]; w2s[tid] = w2[tid]; }

    const float* A0 = feats + (size_t)blockIdx.x * 128 * D_;

    // staging indices
    int ar = tid >> 4, ac4 = tid & 15;   // A: 8 iters x (row, float4-col)
    int bn = tid >> 3, bcu = tid & 7;    // B: 4 iters x (row, 16B-col)

    wmma::fragment<wmma::accumulator, 16, 16, 16, float> cfr[2][4];
    #pragma unroll
    for (int mi = 0; mi < 2; mi++)
        #pragma unroll
        for (int ni = 0; ni < 4; ni++)
            wmma::fill_fragment(cfr[mi][ni], 0.0f);

    auto ldg_a = [&](float4* av, int kc) {
        #pragma unroll
        for (int i = 0; i < 8; i++) {
            int r = ar + i * 16;
            av[i] = __ldg((const float4*)(A0 + (size_t)r * D_ + kc * 64) + ac4);
        }
    };
    auto sts_a = [&](const float4* av, int buf) {
        uint32_t base = sb + (buf ? OFF_A1 : OFF_A0);
        #pragma unroll
        for (int i = 0; i < 8; i++) {
            int r = ar + i * 16;
            uint32_t off = (uint32_t)(r * ROWB + ac4 * 8);
            __half2 h01 = __floats2half2_rn(av[i].x, av[i].y);
            __half2 h23 = __floats2half2_rn(av[i].z, av[i].w);
            asm volatile("st.shared.v2.b32 [%0], {%1, %2};"
                         :: "r"(base + off),
                            "r"(*(uint32_t*)&h01), "r"(*(uint32_t*)&h23) : "memory");
        }
    };
    auto cpa_b = [&](int kc, int buf) {
        uint32_t dbb = sb + (buf ? OFF_BB1 : OFF_BB0);
        #pragma unroll
        for (int i = 0; i < 4; i++) {
            int n = bn + i * 32;
            cpasync16(dbb + (uint32_t)(n * ROWB + bcu * 16),
                      g_w1t + (size_t)n * D_ + kc * 64 + bcu * 8);
        }
        asm volatile("cp.async.commit_group;" ::: "memory");
    };
    auto compute = [&](int buf) {
        const __half* As = (const __half*)(dsm + (buf ? OFF_A1 : OFF_A0));
        const __half* Bs = (const __half*)(dsm + (buf ? OFF_BB1 : OFF_BB0));
        #pragma unroll
        for (int ks = 0; ks < 4; ks++) {
            wmma::fragment<wmma::matrix_a, 16, 16, 16, __half, wmma::row_major> af[2];
            #pragma unroll
            for (int mi = 0; mi < 2; mi++) {
                const __half* pa = As + (size_t)(m_base + mi * 16) * ROWE + ks * 16;
                wmma::load_matrix_sync(af[mi], pa, ROWE);
            }
            #pragma unroll
            for (int ni = 0; ni < 4; ni++) {
                wmma::fragment<wmma::matrix_b, 16, 16, 16, __half, wmma::col_major> bf;
                const __half* pb = Bs + (size_t)(n_base + ni * 16) * ROWE + ks * 16;
                wmma::load_matrix_sync(bf, pb, ROWE);
                #pragma unroll
                for (int mi = 0; mi < 2; mi++)
                    wmma::mma_sync(cfr[mi][ni], af[mi], bf, cfr[mi][ni]);
            }
        }
    };

    // ---- prologue: stage chunk 0 into buffer 0 ----
    {
        float4 av[8];
        cpa_b(0, 0);
        ldg_a(av, 0);
        sts_a(av, 0);
        asm volatile("cp.async.wait_group 0;" ::: "memory");
    }
    __syncthreads();

    // ---- main loop: A and B double-buffered, ONE sync per chunk ----
    #pragma unroll 1
    for (int kc = 0; kc < 16; kc++) {
        int buf = kc & 1;
        float4 av[8];
        if (kc < 15) {
            ldg_a(av, kc + 1);
            cpa_b(kc + 1, buf ^ 1);
        }
        compute(buf);
        if (kc < 15) {
            sts_a(av, buf ^ 1);
            asm volatile("cp.async.wait_group 0;" ::: "memory");
        }
        __syncthreads();
    }

    // ---- epilogue part 1: p(row) = sum_j w2_j * tanh(c + b1_j) ----
    {
        float* ws = scr + warp * 256;
        int r16 = lane & 15, ch = (lane >> 4) * 8;
        float pacc[2] = {0.0f, 0.0f};
        #pragma unroll
        for (int mi = 0; mi < 2; mi++) {
            #pragma unroll
            for (int ni = 0; ni < 4; ni++) {
                wmma::store_matrix_sync(ws, cfr[mi][ni], 16, wmma::mem_row_major);
                __syncwarp();
                float s = 0.0f;
                #pragma unroll
                for (int j = 0; j < 8; j++) {
                    int col = n_base + ni * 16 + ch + j;
                    float v = ws[r16 * 16 + ch + j];
                    s += w2s[col] * tanhf(v + b1s[col]);
                }
                pacc[mi] += s;
                __syncwarp();
            }
        }
        #pragma unroll
        for (int mi = 0; mi < 2; mi++) {
            float tot = pacc[mi] + __shfl_xor_sync(0xffffffffu, pacc[mi], 16);
            if (lane < 16) {
                int row = m_base + mi * 16 + r16;
                part[row * 2 + warp_n] = tot;
            }
        }
    }
    __syncthreads();

    // ---- epilogue part 2: e = mask * exp(logit) ----
    int batch = blockIdx.x >> 6;
    int nidx = ((blockIdx.x & 63) << 7) + tid;
    if (tid < 128) {
        float logit = part[tid * 2] + part[tid * 2 + 1] + b2[0];
        int m = mask[(size_t)batch * N_ + nidx];
        float e = m ? expf(logit) : 0.0f;
        g_e[(size_t)batch * N_ + nidx] = e;
        sa[tid] = e;                 // scr region, safe after part-1 done
    }
    __syncthreads();

    // ---- epilogue part 3: unscaled weighted pool; tile is L2-hot ----
    {
        float4 acc = make_float4(0.f, 0.f, 0.f, 0.f);
        const float4* fp = (const float4*)A0 + tid;   // thread t owns float4-col t
        #pragma unroll 8
        for (int n = 0; n < 128; n++) {
            float a = sa[n];
            float4 v = __ldg(fp + (size_t)n * 256);
            acc.x += a * v.x; acc.y += a * v.y; acc.z += a * v.z; acc.w += a * v.w;
        }
        ((float4*)(g_part + (size_t)blockIdx.x * D_))[tid] = acc;
    }
    __syncthreads();

    // ---- epilogue part 4: per-CTA e sum (tree over sa) ----
    #pragma unroll
    for (int o = 64; o > 0; o >>= 1) {
        if (tid < o) sa[tid] += sa[tid + o];
        __syncthreads();
    }
    if (tid == 0) g_erow[blockIdx.x] = sa[0];
}

// ---------------- kernel 2: per-batch sum of e (deterministic) ----------------
__global__ void esum_kernel() {
    __shared__ float red[64];
    int b = blockIdx.x, t = threadIdx.x;
    red[t] = g_erow[b * CPB + t];
    __syncthreads();
    #pragma unroll
    for (int o = 32; o > 0; o >>= 1) {
        if (t < o) red[t] += red[t + o];
        __syncthreads();
    }
    if (t == 0) g_esum[b] = red[0];
}

// ---------------- kernel 3: attn = e / S ----------------
__global__ void attn_kernel(float* __restrict__ attn) {
    int idx = blockIdx.x * 256 + threadIdx.x;    // 0..B*N-1
    int b = idx >> 13;
    float inv = 1.0f / fmaxf(g_esum[b], 1e-8f);
    attn[idx] = g_e[idx] * inv;
}

// ---------------- kernel 4: pooled = (sum of partials) / S ----------------
__global__ void reduce_kernel(float* __restrict__ pooled) {
    int idx = blockIdx.x * 256 + threadIdx.x;    // 0..B*D-1
    int b = idx >> 10, d = idx & 1023;
    float inv = 1.0f / fmaxf(g_esum[b], 1e-8f);
    float acc = 0.0f;
    #pragma unroll
    for (int s = 0; s < CPB; s++)
        acc += g_part[((size_t)b * CPB + s) * D_ + d];
    pooled[idx] = acc * inv;
}

// ---------------- kernel 5: final classifier ----------------
__global__ void final_kernel(const float* __restrict__ pooled,
                             const float* __restrict__ wc,
                             const float* __restrict__ bc,
                             float* __restrict__ logits) {
    __shared__ float red[256];
    int b = blockIdx.x, t = threadIdx.x;
    float acc = 0.0f;
    #pragma unroll
    for (int j = 0; j < 4; j++) {
        int d = t + j * 256;
        acc += pooled[(size_t)b * D_ + d] * wc[d];
    }
    red[t] = acc; __syncthreads();
    for (int o = 128; o > 0; o >>= 1) { if (t < o) red[t] += red[t + o]; __syncthreads(); }
    if (t == 0) logits[b] = red[0] + bc[0];
}

// ---------------- launch ----------------
extern "C" void kernel_launch(void* const* d_in, const int* in_sizes, int n_in,
                              void* d_out, int out_size) {
    const float* feats = (const float*)d_in[0];
    const int* mask = (const int*)d_in[1];       // jnp.bool_ -> int32
    const float* w1 = (const float*)d_in[2];
    const float* b1 = (const float*)d_in[3];
    const float* w2 = (const float*)d_in[4];
    const float* b2 = (const float*)d_in[5];
    const float* wc = (const float*)d_in[6];
    const float* bc = (const float*)d_in[7];

    float* out = (float*)d_out;
    float* out_logits = out;                 // [B]
    float* out_pooled = out + B_;            // [B, D]
    float* out_attn   = out + B_ + B_ * D_;  // [B, N]

    cudaFuncSetAttribute(gemm1_kernel,
                         cudaFuncAttributeMaxDynamicSharedMemorySize, SMEM_BYTES);

    prep_kernel<<<(H_ * D_) / 256, 256>>>(w1);
    gemm1_kernel<<<(B_ * N_) / 128, 256, SMEM_BYTES>>>(feats, b1, w2, b2, mask);
    esum_kernel<<<B_, CPB>>>();
    attn_kernel<<<(B_ * N_) / 256, 256>>>(out_attn);
    reduce_kernel<<<(B_ * D_) / 256, 256>>>(out_pooled);
    final_kernel<<<B_, 256>>>(out_pooled, wc, bc, out_logits);
}